// round 1
// baseline (speedup 1.0000x reference)
#include <cuda_runtime.h>
#include <cstdint>

// ---------------------------------------------------------------------------
// Problem constants: B=32768, N=17 joints, D=2, K=3, H=64 (k/w MLPs), 2H=128 (b MLP)
// Outputs (flattened float32, concatenated): out (B,N,K,5) | k_js (B,N) | mask (B,N,K)
// ---------------------------------------------------------------------------
#define NB        32768
#define NJ        17
#define TILE_B    32
#define NTILES    (NB / TILE_B)          // 1024
#define NTHREADS  (NJ * 32)              // 544 threads = 17 warps, warp <-> joint

#define JSTRIDE   2836                   // floats per joint in packed weights
#define WFLOATS   (NJ * JSTRIDE)         // 48212 floats = 192848 B

// packed per-joint layout (floats):
//  [0,384):    kMLP rows, 32 rows x 12:  [W1d0 pair, W1d1 pair, W2o0 pair, W2o1 pair, W2o2 pair, b1 pair]
//  [384,768):  wMLP rows, same layout
//  [768,2816): bMLP rows, 64 rows x 32:  [W1d0 pair, W1d1 pair, W2o0..o11 pairs (24), b1 pair, pad(2)]
//  [2816,2819): kb2[3]  [2819,2822): wb2[3]  [2822,2834): bb2[12]  [2834,2836): pad

#define SEC_W     384
#define SEC_B     768
#define OFF_KB2   2816
#define OFF_WB2   2819
#define OFF_BB2   2822

#define OUT_ELEMS   8355840ull           // B*N*K*5
#define KJS_OFF     8355840ull
#define MASK_OFF    8912896ull

// smem: weights (48212 f) + out stage (544*15=8160 f) + kjs bytes(544) + mask bytes(1632)
#define SMEM_BYTES  ((WFLOATS + 8160) * 4 + 544 + 1632)   // 227664 B

typedef unsigned long long ull;

static __device__ __forceinline__ ull pk2(float lo, float hi) {
    ull r; asm("mov.b64 %0,{%1,%2};" : "=l"(r) : "f"(lo), "f"(hi)); return r;
}
static __device__ __forceinline__ ull fma2(ull a, ull b, ull c) {
    ull d; asm("fma.rn.f32x2 %0,%1,%2,%3;" : "=l"(d) : "l"(a), "l"(b), "l"(c)); return d;
}
static __device__ __forceinline__ ull relu2(ull g) {
    float lo, hi; asm("mov.b64 {%0,%1},%2;" : "=f"(lo), "=f"(hi) : "l"(g));
    lo = fmaxf(lo, 0.f); hi = fmaxf(hi, 0.f);
    ull r; asm("mov.b64 %0,{%1,%2};" : "=l"(r) : "f"(lo), "f"(hi)); return r;
}
static __device__ __forceinline__ float rsum2(ull a) {
    float lo, hi; asm("mov.b64 {%0,%1},%2;" : "=f"(lo), "=f"(hi) : "l"(a));
    return lo + hi;
}

__device__ __align__(16) float g_packed[WFLOATS];

// ---------------------------------------------------------------------------
// Setup kernel: pack weights into f32x2-pair friendly, 16B-aligned rows.
// Grid: 17 blocks (one per joint) x 128 threads.
// ---------------------------------------------------------------------------
__global__ void pack_weights(
    const float* __restrict__ kW1, const float* __restrict__ kb1,
    const float* __restrict__ kW2, const float* __restrict__ kb2,
    const float* __restrict__ wW1, const float* __restrict__ wb1,
    const float* __restrict__ wW2, const float* __restrict__ wb2,
    const float* __restrict__ bW1, const float* __restrict__ bb1,
    const float* __restrict__ bW2, const float* __restrict__ bb2)
{
    const int n = blockIdx.x;
    const int t = threadIdx.x;
    float* dst = g_packed + n * JSTRIDE;

    if (t < 32) {                       // kMLP row jp = t
        const int jp = t, j = 2 * jp;
        float* r = dst + jp * 12;
        r[0] = kW1[n * 128 + j];          r[1] = kW1[n * 128 + j + 1];
        r[2] = kW1[n * 128 + 64 + j];     r[3] = kW1[n * 128 + 64 + j + 1];
        #pragma unroll
        for (int o = 0; o < 3; o++) {
            r[4 + 2 * o] = kW2[n * 192 + j * 3 + o];
            r[5 + 2 * o] = kW2[n * 192 + (j + 1) * 3 + o];
        }
        r[10] = kb1[n * 64 + j];          r[11] = kb1[n * 64 + j + 1];
    } else if (t < 64) {                // wMLP row jp = t-32
        const int jp = t - 32, j = 2 * jp;
        float* r = dst + SEC_W + jp * 12;
        r[0] = wW1[n * 128 + j];          r[1] = wW1[n * 128 + j + 1];
        r[2] = wW1[n * 128 + 64 + j];     r[3] = wW1[n * 128 + 64 + j + 1];
        #pragma unroll
        for (int o = 0; o < 3; o++) {
            r[4 + 2 * o] = wW2[n * 192 + j * 3 + o];
            r[5 + 2 * o] = wW2[n * 192 + (j + 1) * 3 + o];
        }
        r[10] = wb1[n * 64 + j];          r[11] = wb1[n * 64 + j + 1];
    } else {                            // bMLP row jp = t-64
        const int jp = t - 64, j = 2 * jp;
        float* r = dst + SEC_B + jp * 32;
        r[0] = bW1[n * 256 + j];          r[1] = bW1[n * 256 + j + 1];
        r[2] = bW1[n * 256 + 128 + j];    r[3] = bW1[n * 256 + 128 + j + 1];
        #pragma unroll
        for (int o = 0; o < 12; o++) {
            r[4 + 2 * o] = bW2[n * 1536 + j * 12 + o];
            r[5 + 2 * o] = bW2[n * 1536 + (j + 1) * 12 + o];
        }
        r[28] = bb1[n * 128 + j];         r[29] = bb1[n * 128 + j + 1];
        r[30] = 0.f; r[31] = 0.f;
    }
    if (t == 0) {
        #pragma unroll
        for (int o = 0; o < 3; o++)  { dst[OFF_KB2 + o] = kb2[n * 3 + o];
                                       dst[OFF_WB2 + o] = wb2[n * 3 + o]; }
        #pragma unroll
        for (int o = 0; o < 12; o++)   dst[OFF_BB2 + o] = bb2[n * 12 + o];
    }
}

// 64-hidden MLP head (k or w): returns 3 logits (bias b2 added by caller).
static __device__ __forceinline__ void mlp64(const float* __restrict__ rows,
                                             ull X0, ull X1, float* o3)
{
    ull a0 = 0, a1 = 0, a2 = 0;
    #pragma unroll 8
    for (int jp = 0; jp < 32; jp++) {
        const float* r = rows + jp * 12;
        ulonglong2 q0 = *(const ulonglong2*)(r);       // W1 d0 pair, d1 pair
        ulonglong2 q1 = *(const ulonglong2*)(r + 4);   // W2 o0, o1 pairs
        ull q2 = *(const ull*)(r + 8);                 // W2 o2 pair
        ull cb = *(const ull*)(r + 10);                // b1 pair
        ull h = relu2(fma2(X0, q0.x, fma2(X1, q0.y, cb)));
        a0 = fma2(h, q1.x, a0);
        a1 = fma2(h, q1.y, a1);
        a2 = fma2(h, q2,   a2);
    }
    o3[0] = rsum2(a0); o3[1] = rsum2(a1); o3[2] = rsum2(a2);
}

// ---------------------------------------------------------------------------
// Main kernel: persistent, 1 block/SM (227.7 KB smem), 17 warps, warp==joint.
// ---------------------------------------------------------------------------
__global__ void __launch_bounds__(NTHREADS, 1)
mlp_main(const float* __restrict__ pred, float* __restrict__ out)
{
    extern __shared__ float sw[];

    // stage all packed weights into smem once (coalesced float4)
    {
        const float4* src = (const float4*)g_packed;
        float4* d4 = (float4*)sw;
        for (int i = threadIdx.x; i < WFLOATS / 4; i += NTHREADS) d4[i] = src[i];
    }
    __syncthreads();

    float* sOut = sw + WFLOATS;                         // 8160 floats
    unsigned char* sK = (unsigned char*)(sOut + 8160);  // 544 bytes
    unsigned char* sM = sK + 544;                       // 1632 bytes

    const int n  = threadIdx.x >> 5;    // joint (warp-uniform)
    const int bx = threadIdx.x & 31;    // batch offset within tile
    const float* jb = sw + n * JSTRIDE;
    const int lp = bx * NJ + n;         // linear point index within tile

    for (int tile = blockIdx.x; tile < NTILES; tile += gridDim.x) {
        const int b0 = tile * TILE_B;
        const int b  = b0 + bx;

        const float2 x = *(const float2*)(pred + (size_t)b * (NJ * 2) + 2 * n);
        const ull X0 = pk2(x.x, x.x);
        const ull X1 = pk2(x.y, x.y);

        // ---- kMLP -> argmax (first-occurrence, matching jnp.argmax) ----
        float kl[3];
        mlp64(jb, X0, X1, kl);
        kl[0] += jb[OFF_KB2]; kl[1] += jb[OFF_KB2 + 1]; kl[2] += jb[OFF_KB2 + 2];
        int am = 0; float bm = kl[0];
        if (kl[1] > bm) { bm = kl[1]; am = 1; }
        if (kl[2] > bm) { bm = kl[2]; am = 2; }

        // ---- wMLP -> softmax ----
        float wl[3];
        mlp64(jb + SEC_W, X0, X1, wl);
        wl[0] += jb[OFF_WB2]; wl[1] += jb[OFF_WB2 + 1]; wl[2] += jb[OFF_WB2 + 2];
        float m = fmaxf(wl[0], fmaxf(wl[1], wl[2]));
        float e0 = expf(wl[0] - m), e1 = expf(wl[1] - m), e2 = expf(wl[2] - m);
        float inv = 1.0f / (e0 + e1 + e2);
        float wv[3] = { e0 * inv, e1 * inv, e2 * inv };

        // ---- bMLP (2 -> 128 -> 12) ----
        ull acc[12];
        #pragma unroll
        for (int o = 0; o < 12; o++) acc[o] = 0;
        #pragma unroll 4
        for (int jp = 0; jp < 64; jp++) {
            const float* r = jb + SEC_B + jp * 32;
            ulonglong2 q0 = *(const ulonglong2*)(r);        // W1 pairs
            ulonglong2 q1 = *(const ulonglong2*)(r + 4);    // W2 o0,o1
            ulonglong2 q2 = *(const ulonglong2*)(r + 8);    // o2,o3
            ulonglong2 q3 = *(const ulonglong2*)(r + 12);   // o4,o5
            ulonglong2 q4 = *(const ulonglong2*)(r + 16);   // o6,o7
            ulonglong2 q5 = *(const ulonglong2*)(r + 20);   // o8,o9
            ulonglong2 q6 = *(const ulonglong2*)(r + 24);   // o10,o11
            ull cb = *(const ull*)(r + 28);                 // b1 pair
            ull h = relu2(fma2(X0, q0.x, fma2(X1, q0.y, cb)));
            acc[0]  = fma2(h, q1.x, acc[0]);  acc[1]  = fma2(h, q1.y, acc[1]);
            acc[2]  = fma2(h, q2.x, acc[2]);  acc[3]  = fma2(h, q2.y, acc[3]);
            acc[4]  = fma2(h, q3.x, acc[4]);  acc[5]  = fma2(h, q3.y, acc[5]);
            acc[6]  = fma2(h, q4.x, acc[6]);  acc[7]  = fma2(h, q4.y, acc[7]);
            acc[8]  = fma2(h, q5.x, acc[8]);  acc[9]  = fma2(h, q5.y, acc[9]);
            acc[10] = fma2(h, q6.x, acc[10]); acc[11] = fma2(h, q6.y, acc[11]);
        }
        float pv[12];
        #pragma unroll
        for (int o = 0; o < 12; o++) pv[o] = rsum2(acc[o]) + jb[OFF_BB2 + o];

        // payload = (mu0, mu1, sigma0, sigma1) per mixture component
        float4 pl[3];
        float ws[3];
        #pragma unroll
        for (int k = 0; k < 3; k++) {
            pl[k] = make_float4(pv[4 * k], pv[4 * k + 1],
                                expf(pv[4 * k + 2]), expf(pv[4 * k + 3]));
            ws[k] = wv[k];
        }
        // stable descending sort by w (ties keep ascending index) — matches
        // stable jnp.argsort(-w). Bubble network (0,1),(1,2),(0,1), strict >.
        #define CSWAP(i, j)                                                 \
            if (ws[j] > ws[i]) {                                            \
                float tw = ws[i]; ws[i] = ws[j]; ws[j] = tw;                \
                float4 tp = pl[i]; pl[i] = pl[j]; pl[j] = tp;               \
            }
        CSWAP(0, 1) CSWAP(1, 2) CSWAP(0, 1)
        #undef CSWAP

        // ---- stage results in smem ----
        float* op = sOut + lp * 15;
        #pragma unroll
        for (int k = 0; k < 3; k++) {
            op[5 * k + 0] = wv[k];        // unsorted w (out[...,0] = w)
            op[5 * k + 1] = pl[k].x;      // mu_top
            op[5 * k + 2] = pl[k].y;
            op[5 * k + 3] = pl[k].z;      // sigma_top
            op[5 * k + 4] = pl[k].w;
        }
        sK[lp] = (unsigned char)(am + 1);
        #pragma unroll
        for (int k = 0; k < 3; k++) sM[3 * lp + k] = (k <= am) ? 1 : 0;

        __syncthreads();

        // ---- cooperative coalesced stores ----
        const size_t p0 = (size_t)b0 * NJ;
        {
            float4* go = (float4*)(out + p0 * 15);
            const float4* so = (const float4*)sOut;
            for (int i = threadIdx.x; i < 2040; i += NTHREADS) go[i] = so[i];
        }
        out[KJS_OFF + p0 + threadIdx.x] = (float)sK[threadIdx.x];
        {
            float* gm = out + MASK_OFF + p0 * 3;
            for (int i = threadIdx.x; i < 3 * NTHREADS; i += NTHREADS)
                gm[i] = (float)sM[i];
        }
        __syncthreads();
    }
}

// ---------------------------------------------------------------------------
extern "C" void kernel_launch(void* const* d_in, const int* in_sizes, int n_in,
                              void* d_out, int out_size)
{
    const float* pred = (const float*)d_in[0];
    const float* kW1 = (const float*)d_in[1];
    const float* kb1 = (const float*)d_in[2];
    const float* kW2 = (const float*)d_in[3];
    const float* kb2 = (const float*)d_in[4];
    const float* wW1 = (const float*)d_in[5];
    const float* wb1 = (const float*)d_in[6];
    const float* wW2 = (const float*)d_in[7];
    const float* wb2 = (const float*)d_in[8];
    const float* bW1 = (const float*)d_in[9];
    const float* bb1 = (const float*)d_in[10];
    const float* bW2 = (const float*)d_in[11];
    const float* bb2 = (const float*)d_in[12];
    float* out = (float*)d_out;

    pack_weights<<<NJ, 128>>>(kW1, kb1, kW2, kb2,
                              wW1, wb1, wW2, wb2,
                              bW1, bb1, bW2, bb2);

    cudaFuncSetAttribute(mlp_main,
                         cudaFuncAttributeMaxDynamicSharedMemorySize,
                         SMEM_BYTES);

    int dev = 0;
    cudaGetDevice(&dev);
    int nsm = 148;
    cudaDeviceGetAttribute(&nsm, cudaDevAttrMultiProcessorCount, dev);
    int grid = (nsm < NTILES) ? nsm : NTILES;

    mlp_main<<<grid, NTHREADS, SMEM_BYTES>>>(pred, out);
}

// round 2
// speedup vs baseline: 1.0187x; 1.0187x over previous
#include <cuda_runtime.h>
#include <cstdint>

// ---------------------------------------------------------------------------
// B=32768, N=17 joints, D=2, K=3, H=64 (k/w MLPs), 2H=128 (b MLP)
// Outputs (flattened float32): out (B,N,K,5) | k_js (B,N) | mask (B,N,K)
// ---------------------------------------------------------------------------
#define NB        32768
#define NJ        17
#define TILE_B    32
#define NTILES    (NB / TILE_B)          // 1024
#define NPAIRS    (NTILES / 2)           // 512
#define NTHREADS  (NJ * 32)              // 544 threads = 17 warps, warp <-> joint

#define JSTRIDE   2836                   // floats per joint in packed weights
#define WFLOATS   (NJ * JSTRIDE)         // 48212 floats = 192848 B

// packed per-joint layout (floats):
//  [0,384):    kMLP rows, 32 rows x 12: [W1d0 pair, W1d1 pair | W2o0 pair, W2o1 pair | W2o2 pair, b1 pair]
//  [384,768):  wMLP rows, same
//  [768,2816): bMLP rows, 64 rows x 32: [W1 pairs(4) | W2 o0..o11 pairs (24) | b1 pair, pad(2)]
//  [2816,2819): kb2[3]  [2819,2822): wb2[3]  [2822,2834): bb2[12]

#define SEC_W     384
#define SEC_B     768
#define OFF_KB2   2816
#define OFF_WB2   2819
#define OFF_BB2   2822

#define KJS_OFF     8355840ull           // B*N*K*5
#define MASK_OFF    8912896ull

// smem: weights + out stage (544*15) + kjs bytes + mask bytes
#define SMEM_BYTES  ((WFLOATS + 8160) * 4 + 544 + 1632)   // 227664 B

typedef unsigned long long ull;

static __device__ __forceinline__ ull pk2(float lo, float hi) {
    ull r; asm("mov.b64 %0,{%1,%2};" : "=l"(r) : "f"(lo), "f"(hi)); return r;
}
static __device__ __forceinline__ ull fma2(ull a, ull b, ull c) {
    ull d; asm("fma.rn.f32x2 %0,%1,%2,%3;" : "=l"(d) : "l"(a), "l"(b), "l"(c)); return d;
}
static __device__ __forceinline__ ull relu2(ull g) {
    float lo, hi; asm("mov.b64 {%0,%1},%2;" : "=f"(lo), "=f"(hi) : "l"(g));
    lo = fmaxf(lo, 0.f); hi = fmaxf(hi, 0.f);
    ull r; asm("mov.b64 %0,{%1,%2};" : "=l"(r) : "f"(lo), "f"(hi)); return r;
}
static __device__ __forceinline__ float rsum2(ull a) {
    float lo, hi; asm("mov.b64 {%0,%1},%2;" : "=f"(lo), "=f"(hi) : "l"(a));
    return lo + hi;
}

__device__ __align__(16) float g_packed[WFLOATS];

// ---------------------------------------------------------------------------
// Setup kernel: pack weights (17 blocks x 128 threads).
// ---------------------------------------------------------------------------
__global__ void pack_weights(
    const float* __restrict__ kW1, const float* __restrict__ kb1,
    const float* __restrict__ kW2, const float* __restrict__ kb2,
    const float* __restrict__ wW1, const float* __restrict__ wb1,
    const float* __restrict__ wW2, const float* __restrict__ wb2,
    const float* __restrict__ bW1, const float* __restrict__ bb1,
    const float* __restrict__ bW2, const float* __restrict__ bb2)
{
    const int n = blockIdx.x;
    const int t = threadIdx.x;
    float* dst = g_packed + n * JSTRIDE;

    if (t < 32) {                       // kMLP row jp = t
        const int jp = t, j = 2 * jp;
        float* r = dst + jp * 12;
        r[0] = kW1[n * 128 + j];          r[1] = kW1[n * 128 + j + 1];
        r[2] = kW1[n * 128 + 64 + j];     r[3] = kW1[n * 128 + 64 + j + 1];
        #pragma unroll
        for (int o = 0; o < 3; o++) {
            r[4 + 2 * o] = kW2[n * 192 + j * 3 + o];
            r[5 + 2 * o] = kW2[n * 192 + (j + 1) * 3 + o];
        }
        r[10] = kb1[n * 64 + j];          r[11] = kb1[n * 64 + j + 1];
    } else if (t < 64) {                // wMLP row jp = t-32
        const int jp = t - 32, j = 2 * jp;
        float* r = dst + SEC_W + jp * 12;
        r[0] = wW1[n * 128 + j];          r[1] = wW1[n * 128 + j + 1];
        r[2] = wW1[n * 128 + 64 + j];     r[3] = wW1[n * 128 + 64 + j + 1];
        #pragma unroll
        for (int o = 0; o < 3; o++) {
            r[4 + 2 * o] = wW2[n * 192 + j * 3 + o];
            r[5 + 2 * o] = wW2[n * 192 + (j + 1) * 3 + o];
        }
        r[10] = wb1[n * 64 + j];          r[11] = wb1[n * 64 + j + 1];
    } else {                            // bMLP row jp = t-64
        const int jp = t - 64, j = 2 * jp;
        float* r = dst + SEC_B + jp * 32;
        r[0] = bW1[n * 256 + j];          r[1] = bW1[n * 256 + j + 1];
        r[2] = bW1[n * 256 + 128 + j];    r[3] = bW1[n * 256 + 128 + j + 1];
        #pragma unroll
        for (int o = 0; o < 12; o++) {
            r[4 + 2 * o] = bW2[n * 1536 + j * 12 + o];
            r[5 + 2 * o] = bW2[n * 1536 + (j + 1) * 12 + o];
        }
        r[28] = bb1[n * 128 + j];         r[29] = bb1[n * 128 + j + 1];
        r[30] = 0.f; r[31] = 0.f;
    }
    if (t == 0) {
        #pragma unroll
        for (int o = 0; o < 3; o++)  { dst[OFF_KB2 + o] = kb2[n * 3 + o];
                                       dst[OFF_WB2 + o] = wb2[n * 3 + o]; }
        #pragma unroll
        for (int o = 0; o < 12; o++)   dst[OFF_BB2 + o] = bb2[n * 12 + o];
    }
}

// Dual-point 64-hidden MLP head (k or w): exactly 3x LDS.128 per row.
static __device__ __forceinline__ void mlp64_2(const float* __restrict__ rows,
                                               ull X0a, ull X1a, ull X0b, ull X1b,
                                               float* oa, float* ob)
{
    ull a0 = 0, a1 = 0, a2 = 0, c0 = 0, c1 = 0, c2 = 0;
    #pragma unroll 4
    for (int jp = 0; jp < 32; jp++) {
        const float* r = rows + jp * 12;
        ulonglong2 q0 = *(const ulonglong2*)(r);       // W1 d0 pair, d1 pair
        ulonglong2 q1 = *(const ulonglong2*)(r + 4);   // W2 o0, o1 pairs
        ulonglong2 q2 = *(const ulonglong2*)(r + 8);   // W2 o2 pair, b1 pair
        ull ha = relu2(fma2(X0a, q0.x, fma2(X1a, q0.y, q2.y)));
        ull hb = relu2(fma2(X0b, q0.x, fma2(X1b, q0.y, q2.y)));
        a0 = fma2(ha, q1.x, a0);  c0 = fma2(hb, q1.x, c0);
        a1 = fma2(ha, q1.y, a1);  c1 = fma2(hb, q1.y, c1);
        a2 = fma2(ha, q2.x, a2);  c2 = fma2(hb, q2.x, c2);
    }
    oa[0] = rsum2(a0); oa[1] = rsum2(a1); oa[2] = rsum2(a2);
    ob[0] = rsum2(c0); ob[1] = rsum2(c1); ob[2] = rsum2(c2);
}

// Per-point epilogue: argmax, softmax, exp(sigma), stable descending sort.
static __device__ __forceinline__ void finish(const float kl[3], const float wl[3],
                                              const float pv[12],
                                              float v[15], int& am)
{
    am = 0; float bm = kl[0];
    if (kl[1] > bm) { bm = kl[1]; am = 1; }
    if (kl[2] > bm) { bm = kl[2]; am = 2; }

    float m  = fmaxf(wl[0], fmaxf(wl[1], wl[2]));
    float e0 = expf(wl[0] - m), e1 = expf(wl[1] - m), e2 = expf(wl[2] - m);
    float inv = 1.0f / (e0 + e1 + e2);
    float wv[3] = { e0 * inv, e1 * inv, e2 * inv };

    float4 pl[3]; float ws[3];
    #pragma unroll
    for (int k = 0; k < 3; k++) {
        pl[k] = make_float4(pv[4 * k], pv[4 * k + 1],
                            expf(pv[4 * k + 2]), expf(pv[4 * k + 3]));
        ws[k] = wv[k];
    }
    // stable descending sort by w (strict >): matches stable jnp.argsort(-w)
    #define CSWAP(i, j)                                                 \
        if (ws[j] > ws[i]) {                                            \
            float tw = ws[i]; ws[i] = ws[j]; ws[j] = tw;                \
            float4 tp = pl[i]; pl[i] = pl[j]; pl[j] = tp;               \
        }
    CSWAP(0, 1) CSWAP(1, 2) CSWAP(0, 1)
    #undef CSWAP

    #pragma unroll
    for (int k = 0; k < 3; k++) {
        v[5 * k + 0] = wv[k];
        v[5 * k + 1] = pl[k].x;
        v[5 * k + 2] = pl[k].y;
        v[5 * k + 3] = pl[k].z;
        v[5 * k + 4] = pl[k].w;
    }
}

// ---------------------------------------------------------------------------
// Main kernel: persistent, 1 block/SM, 17 warps, warp==joint, 2 points/thread.
// ---------------------------------------------------------------------------
__global__ void __launch_bounds__(NTHREADS, 1)
mlp_main(const float* __restrict__ pred, float* __restrict__ out)
{
    extern __shared__ float sw[];

    {   // stage packed weights into smem once (coalesced float4)
        const float4* src = (const float4*)g_packed;
        float4* d4 = (float4*)sw;
        for (int i = threadIdx.x; i < WFLOATS / 4; i += NTHREADS) d4[i] = src[i];
    }
    __syncthreads();

    float* sOut = sw + WFLOATS;                         // 8160 floats
    unsigned char* sK = (unsigned char*)(sOut + 8160);  // 544 bytes
    unsigned char* sM = sK + 544;                       // 1632 bytes

    const int n  = threadIdx.x >> 5;    // joint (warp-uniform)
    const int bx = threadIdx.x & 31;    // batch offset within tile
    const float* jb = sw + n * JSTRIDE;
    const int lp = bx * NJ + n;         // linear point index within tile

    const float kb2a = jb[OFF_KB2], kb2b = jb[OFF_KB2 + 1], kb2c = jb[OFF_KB2 + 2];
    const float wb2a = jb[OFF_WB2], wb2b = jb[OFF_WB2 + 1], wb2c = jb[OFF_WB2 + 2];

    for (int it = blockIdx.x; it < NPAIRS; it += gridDim.x) {
        const int ta = 2 * it, tb = ta + 1;
        const int ba = ta * TILE_B + bx;
        const int bb = tb * TILE_B + bx;

        const float2 xa = *(const float2*)(pred + (size_t)ba * (NJ * 2) + 2 * n);
        const float2 xb = *(const float2*)(pred + (size_t)bb * (NJ * 2) + 2 * n);
        const ull X0a = pk2(xa.x, xa.x), X1a = pk2(xa.y, xa.y);
        const ull X0b = pk2(xb.x, xb.x), X1b = pk2(xb.y, xb.y);

        // ---- kMLP ----
        float kla[3], klb[3];
        mlp64_2(jb, X0a, X1a, X0b, X1b, kla, klb);
        kla[0] += kb2a; kla[1] += kb2b; kla[2] += kb2c;
        klb[0] += kb2a; klb[1] += kb2b; klb[2] += kb2c;

        // ---- wMLP ----
        float wla[3], wlb[3];
        mlp64_2(jb + SEC_W, X0a, X1a, X0b, X1b, wla, wlb);
        wla[0] += wb2a; wla[1] += wb2b; wla[2] += wb2c;
        wlb[0] += wb2a; wlb[1] += wb2b; wlb[2] += wb2c;

        // ---- bMLP (2 -> 128 -> 12), dual point ----
        ull acca[12], accb[12];
        #pragma unroll
        for (int o = 0; o < 12; o++) { acca[o] = 0; accb[o] = 0; }
        #pragma unroll 2
        for (int jp = 0; jp < 64; jp++) {
            const float* r = jb + SEC_B + jp * 32;
            ulonglong2 q0 = *(const ulonglong2*)(r);        // W1 pairs
            ulonglong2 q1 = *(const ulonglong2*)(r + 4);    // W2 o0,o1
            ulonglong2 q2 = *(const ulonglong2*)(r + 8);    // o2,o3
            ulonglong2 q3 = *(const ulonglong2*)(r + 12);   // o4,o5
            ulonglong2 q4 = *(const ulonglong2*)(r + 16);   // o6,o7
            ulonglong2 q5 = *(const ulonglong2*)(r + 20);   // o8,o9
            ulonglong2 q6 = *(const ulonglong2*)(r + 24);   // o10,o11
            ull cb = *(const ull*)(r + 28);                 // b1 pair
            ull ha = relu2(fma2(X0a, q0.x, fma2(X1a, q0.y, cb)));
            ull hb = relu2(fma2(X0b, q0.x, fma2(X1b, q0.y, cb)));
            acca[0]  = fma2(ha, q1.x, acca[0]);  accb[0]  = fma2(hb, q1.x, accb[0]);
            acca[1]  = fma2(ha, q1.y, acca[1]);  accb[1]  = fma2(hb, q1.y, accb[1]);
            acca[2]  = fma2(ha, q2.x, acca[2]);  accb[2]  = fma2(hb, q2.x, accb[2]);
            acca[3]  = fma2(ha, q2.y, acca[3]);  accb[3]  = fma2(hb, q2.y, accb[3]);
            acca[4]  = fma2(ha, q3.x, acca[4]);  accb[4]  = fma2(hb, q3.x, accb[4]);
            acca[5]  = fma2(ha, q3.y, acca[5]);  accb[5]  = fma2(hb, q3.y, accb[5]);
            acca[6]  = fma2(ha, q4.x, acca[6]);  accb[6]  = fma2(hb, q4.x, accb[6]);
            acca[7]  = fma2(ha, q4.y, acca[7]);  accb[7]  = fma2(hb, q4.y, accb[7]);
            acca[8]  = fma2(ha, q5.x, acca[8]);  accb[8]  = fma2(hb, q5.x, accb[8]);
            acca[9]  = fma2(ha, q5.y, acca[9]);  accb[9]  = fma2(hb, q5.y, accb[9]);
            acca[10] = fma2(ha, q6.x, acca[10]); accb[10] = fma2(hb, q6.x, accb[10]);
            acca[11] = fma2(ha, q6.y, acca[11]); accb[11] = fma2(hb, q6.y, accb[11]);
        }
        float pva[12], pvb[12];
        #pragma unroll
        for (int o = 0; o < 12; o++) {
            const float bias = jb[OFF_BB2 + o];
            pva[o] = rsum2(acca[o]) + bias;
            pvb[o] = rsum2(accb[o]) + bias;
        }

        float va[15], vb[15]; int ama, amb;
        finish(kla, wla, pva, va, ama);
        finish(klb, wlb, pvb, vb, amb);

        // ---- tile a: stage + coalesced store ----
        {
            float* op = sOut + lp * 15;
            #pragma unroll
            for (int k = 0; k < 15; k++) op[k] = va[k];
            sK[lp] = (unsigned char)(ama + 1);
            #pragma unroll
            for (int k = 0; k < 3; k++) sM[3 * lp + k] = (k <= ama) ? 1 : 0;
        }
        __syncthreads();
        {
            const size_t p0 = (size_t)ta * TILE_B * NJ;
            float4* go = (float4*)(out + p0 * 15);
            const float4* so = (const float4*)sOut;
            for (int i = threadIdx.x; i < 2040; i += NTHREADS) go[i] = so[i];
            out[KJS_OFF + p0 + threadIdx.x] = (float)sK[threadIdx.x];
            float* gm = out + MASK_OFF + p0 * 3;
            for (int i = threadIdx.x; i < 3 * NTHREADS; i += NTHREADS)
                gm[i] = (float)sM[i];
        }
        __syncthreads();

        // ---- tile b: stage + coalesced store ----
        {
            float* op = sOut + lp * 15;
            #pragma unroll
            for (int k = 0; k < 15; k++) op[k] = vb[k];
            sK[lp] = (unsigned char)(amb + 1);
            #pragma unroll
            for (int k = 0; k < 3; k++) sM[3 * lp + k] = (k <= amb) ? 1 : 0;
        }
        __syncthreads();
        {
            const size_t p0 = (size_t)tb * TILE_B * NJ;
            float4* go = (float4*)(out + p0 * 15);
            const float4* so = (const float4*)sOut;
            for (int i = threadIdx.x; i < 2040; i += NTHREADS) go[i] = so[i];
            out[KJS_OFF + p0 + threadIdx.x] = (float)sK[threadIdx.x];
            float* gm = out + MASK_OFF + p0 * 3;
            for (int i = threadIdx.x; i < 3 * NTHREADS; i += NTHREADS)
                gm[i] = (float)sM[i];
        }
        __syncthreads();
    }
}

// ---------------------------------------------------------------------------
extern "C" void kernel_launch(void* const* d_in, const int* in_sizes, int n_in,
                              void* d_out, int out_size)
{
    const float* pred = (const float*)d_in[0];
    const float* kW1 = (const float*)d_in[1];
    const float* kb1 = (const float*)d_in[2];
    const float* kW2 = (const float*)d_in[3];
    const float* kb2 = (const float*)d_in[4];
    const float* wW1 = (const float*)d_in[5];
    const float* wb1 = (const float*)d_in[6];
    const float* wW2 = (const float*)d_in[7];
    const float* wb2 = (const float*)d_in[8];
    const float* bW1 = (const float*)d_in[9];
    const float* bb1 = (const float*)d_in[10];
    const float* bW2 = (const float*)d_in[11];
    const float* bb2 = (const float*)d_in[12];
    float* out = (float*)d_out;

    pack_weights<<<NJ, 128>>>(kW1, kb1, kW2, kb2,
                              wW1, wb1, wW2, wb2,
                              bW1, bb1, bW2, bb2);

    cudaFuncSetAttribute(mlp_main,
                         cudaFuncAttributeMaxDynamicSharedMemorySize,
                         SMEM_BYTES);

    int dev = 0;
    cudaGetDevice(&dev);
    int nsm = 148;
    cudaDeviceGetAttribute(&nsm, cudaDevAttrMultiProcessorCount, dev);
    int grid = (nsm < NPAIRS) ? nsm : NPAIRS;

    mlp_main<<<grid, NTHREADS, SMEM_BYTES>>>(pred, out);
}

// round 3
// speedup vs baseline: 1.0885x; 1.0685x over previous
#include <cuda_runtime.h>
#include <cstdint>

// ---------------------------------------------------------------------------
// B=32768, N=17 joints, D=2, K=3, H=64 (k/w MLPs), 2H=128 (b MLP)
// Outputs (flattened float32): out (B,N,K,5) | k_js (B,N) | mask (B,N,K)
// ---------------------------------------------------------------------------
#define NB        32768
#define NJ        17
#define TILE_B    32
#define NTILES    (NB / TILE_B)          // 1024
#define NBJ       34                     // blocks per joint
#define ITERS     4                      // units per warp (guarded)

#define JSTRIDE   2836                   // floats per joint in packed weights
#define WFLOATS   (NJ * JSTRIDE)

// packed per-joint layout (floats):
//  [0,384):    kMLP rows, 32 rows x 12: [W1d0 pair, W1d1 pair | W2o0, W2o1 | W2o2, b1]
//  [384,768):  wMLP rows, same
//  [768,2816): bMLP rows, 64 rows x 32: [W1 pairs(4) | W2 o0..o11 pairs (24) | b1 pair, pad]
//  [2816,2819): kb2[3]  [2819,2822): wb2[3]  [2822,2834): bb2[12]
#define SEC_W     384
#define SEC_B     768
#define OFF_KB2   2816
#define OFF_WB2   2819
#define OFF_BB2   2822

#define KJS_OFF     8355840ull           // B*N*K*5
#define MASK_OFF    8912896ull

typedef unsigned long long ull;

static __device__ __forceinline__ ull pk2(float lo, float hi) {
    ull r; asm("mov.b64 %0,{%1,%2};" : "=l"(r) : "f"(lo), "f"(hi)); return r;
}
static __device__ __forceinline__ ull fma2(ull a, ull b, ull c) {
    ull d; asm("fma.rn.f32x2 %0,%1,%2,%3;" : "=l"(d) : "l"(a), "l"(b), "l"(c)); return d;
}
static __device__ __forceinline__ ull relu2(ull g) {
    float lo, hi; asm("mov.b64 {%0,%1},%2;" : "=f"(lo), "=f"(hi) : "l"(g));
    lo = fmaxf(lo, 0.f); hi = fmaxf(hi, 0.f);
    ull r; asm("mov.b64 %0,{%1,%2};" : "=l"(r) : "f"(lo), "f"(hi)); return r;
}
static __device__ __forceinline__ float rsum2(ull a) {
    float lo, hi; asm("mov.b64 {%0,%1},%2;" : "=f"(lo), "=f"(hi) : "l"(a));
    return lo + hi;
}

__device__ __align__(16) float g_packed[WFLOATS];

// ---------------------------------------------------------------------------
// Setup kernel: pack weights into f32x2-pair rows (17 blocks x 128 threads).
// ---------------------------------------------------------------------------
__global__ void pack_weights(
    const float* __restrict__ kW1, const float* __restrict__ kb1,
    const float* __restrict__ kW2, const float* __restrict__ kb2,
    const float* __restrict__ wW1, const float* __restrict__ wb1,
    const float* __restrict__ wW2, const float* __restrict__ wb2,
    const float* __restrict__ bW1, const float* __restrict__ bb1,
    const float* __restrict__ bW2, const float* __restrict__ bb2)
{
    const int n = blockIdx.x;
    const int t = threadIdx.x;
    float* dst = g_packed + n * JSTRIDE;

    if (t < 32) {                       // kMLP row jp = t
        const int jp = t, j = 2 * jp;
        float* r = dst + jp * 12;
        r[0] = kW1[n * 128 + j];          r[1] = kW1[n * 128 + j + 1];
        r[2] = kW1[n * 128 + 64 + j];     r[3] = kW1[n * 128 + 64 + j + 1];
        #pragma unroll
        for (int o = 0; o < 3; o++) {
            r[4 + 2 * o] = kW2[n * 192 + j * 3 + o];
            r[5 + 2 * o] = kW2[n * 192 + (j + 1) * 3 + o];
        }
        r[10] = kb1[n * 64 + j];          r[11] = kb1[n * 64 + j + 1];
    } else if (t < 64) {                // wMLP row jp = t-32
        const int jp = t - 32, j = 2 * jp;
        float* r = dst + SEC_W + jp * 12;
        r[0] = wW1[n * 128 + j];          r[1] = wW1[n * 128 + j + 1];
        r[2] = wW1[n * 128 + 64 + j];     r[3] = wW1[n * 128 + 64 + j + 1];
        #pragma unroll
        for (int o = 0; o < 3; o++) {
            r[4 + 2 * o] = wW2[n * 192 + j * 3 + o];
            r[5 + 2 * o] = wW2[n * 192 + (j + 1) * 3 + o];
        }
        r[10] = wb1[n * 64 + j];          r[11] = wb1[n * 64 + j + 1];
    } else {                            // bMLP row jp = t-64
        const int jp = t - 64, j = 2 * jp;
        float* r = dst + SEC_B + jp * 32;
        r[0] = bW1[n * 256 + j];          r[1] = bW1[n * 256 + j + 1];
        r[2] = bW1[n * 256 + 128 + j];    r[3] = bW1[n * 256 + 128 + j + 1];
        #pragma unroll
        for (int o = 0; o < 12; o++) {
            r[4 + 2 * o] = bW2[n * 1536 + j * 12 + o];
            r[5 + 2 * o] = bW2[n * 1536 + (j + 1) * 12 + o];
        }
        r[28] = bb1[n * 128 + j];         r[29] = bb1[n * 128 + j + 1];
        r[30] = 0.f; r[31] = 0.f;
    }
    if (t == 0) {
        #pragma unroll
        for (int o = 0; o < 3; o++)  { dst[OFF_KB2 + o] = kb2[n * 3 + o];
                                       dst[OFF_WB2 + o] = wb2[n * 3 + o]; }
        #pragma unroll
        for (int o = 0; o < 12; o++)   dst[OFF_BB2 + o] = bb2[n * 12 + o];
    }
}

// 64-hidden MLP head (k or w): 3 LDS.128 per row, 5 fma2 + relu.
static __device__ __forceinline__ void mlp64(const float* __restrict__ rows,
                                             ull X0, ull X1, float* o3)
{
    ull a0 = 0, a1 = 0, a2 = 0;
    #pragma unroll 8
    for (int jp = 0; jp < 32; jp++) {
        const float* r = rows + jp * 12;
        ulonglong2 q0 = *(const ulonglong2*)(r);       // W1 d0 pair, d1 pair
        ulonglong2 q1 = *(const ulonglong2*)(r + 4);   // W2 o0, o1 pairs
        ulonglong2 q2 = *(const ulonglong2*)(r + 8);   // W2 o2 pair, b1 pair
        ull h = relu2(fma2(X0, q0.x, fma2(X1, q0.y, q2.y)));
        a0 = fma2(h, q1.x, a0);
        a1 = fma2(h, q1.y, a1);
        a2 = fma2(h, q2.x, a2);
    }
    o3[0] = rsum2(a0); o3[1] = rsum2(a1); o3[2] = rsum2(a2);
}

// ---------------------------------------------------------------------------
// Main kernel: 1 joint/block, 256 threads (8 warps), 4 blocks/SM -> 32 warps.
// Warps fully independent after weight staging (no __syncthreads in loop).
// ---------------------------------------------------------------------------
__global__ void __launch_bounds__(256, 4)
mlp_main(const float* __restrict__ pred, float* __restrict__ out)
{
    __shared__ float swt[JSTRIDE];                 // this joint's packed weights
    __shared__ float sStage[8][32 * 17];           // per-warp staging, pad 17

    const int joint = blockIdx.x % NJ;
    const int blk   = blockIdx.x / NJ;             // 0..33
    const int wid   = threadIdx.x >> 5;
    const int lane  = threadIdx.x & 31;

    {   // stage this joint's weights into smem (coalesced float4)
        const float4* src = (const float4*)(g_packed + joint * JSTRIDE);
        float4* dst = (float4*)swt;
        #pragma unroll
        for (int i = threadIdx.x; i < JSTRIDE / 4; i += 256) dst[i] = src[i];
    }
    __syncthreads();

    const float kb2a = swt[OFF_KB2], kb2b = swt[OFF_KB2 + 1], kb2c = swt[OFF_KB2 + 2];
    const float wb2a = swt[OFF_WB2], wb2b = swt[OFF_WB2 + 1], wb2c = swt[OFF_WB2 + 2];

    float* myStage = sStage[wid];
    const int j15 = lane & 15;
    const int hi  = lane >> 4;          // 0 for lanes 0-15, 1 for 16-31

    for (int i = 0; i < ITERS; i++) {
        const int tile = blk + NBJ * (wid + 8 * i);
        if (tile >= NTILES) break;

        const int b = tile * TILE_B + lane;
        const float2 x = *(const float2*)(pred + ((size_t)b * NJ + joint) * 2);
        const ull X0 = pk2(x.x, x.x);
        const ull X1 = pk2(x.y, x.y);

        // ---- kMLP -> argmax (first occurrence, matches jnp.argmax) ----
        float kl[3];
        mlp64(swt, X0, X1, kl);
        kl[0] += kb2a; kl[1] += kb2b; kl[2] += kb2c;
        int am = 0; float bm = kl[0];
        if (kl[1] > bm) { bm = kl[1]; am = 1; }
        if (kl[2] > bm) { bm = kl[2]; am = 2; }

        // ---- wMLP -> softmax ----
        float wl[3];
        mlp64(swt + SEC_W, X0, X1, wl);
        wl[0] += wb2a; wl[1] += wb2b; wl[2] += wb2c;
        float m  = fmaxf(wl[0], fmaxf(wl[1], wl[2]));
        float e0 = expf(wl[0] - m), e1 = expf(wl[1] - m), e2 = expf(wl[2] - m);
        float inv = 1.0f / (e0 + e1 + e2);
        float wv[3] = { e0 * inv, e1 * inv, e2 * inv };

        // ---- bMLP (2 -> 128 -> 12) ----
        ull acc[12];
        #pragma unroll
        for (int o = 0; o < 12; o++) acc[o] = 0;
        #pragma unroll 4
        for (int jp = 0; jp < 64; jp++) {
            const float* r = swt + SEC_B + jp * 32;
            ulonglong2 q0 = *(const ulonglong2*)(r);
            ulonglong2 q1 = *(const ulonglong2*)(r + 4);
            ulonglong2 q2 = *(const ulonglong2*)(r + 8);
            ulonglong2 q3 = *(const ulonglong2*)(r + 12);
            ulonglong2 q4 = *(const ulonglong2*)(r + 16);
            ulonglong2 q5 = *(const ulonglong2*)(r + 20);
            ulonglong2 q6 = *(const ulonglong2*)(r + 24);
            ull cb = *(const ull*)(r + 28);
            ull h = relu2(fma2(X0, q0.x, fma2(X1, q0.y, cb)));
            acc[0]  = fma2(h, q1.x, acc[0]);
            acc[1]  = fma2(h, q1.y, acc[1]);
            acc[2]  = fma2(h, q2.x, acc[2]);
            acc[3]  = fma2(h, q2.y, acc[3]);
            acc[4]  = fma2(h, q3.x, acc[4]);
            acc[5]  = fma2(h, q3.y, acc[5]);
            acc[6]  = fma2(h, q4.x, acc[6]);
            acc[7]  = fma2(h, q4.y, acc[7]);
            acc[8]  = fma2(h, q5.x, acc[8]);
            acc[9]  = fma2(h, q5.y, acc[9]);
            acc[10] = fma2(h, q6.x, acc[10]);
            acc[11] = fma2(h, q6.y, acc[11]);
        }
        float pv[12];
        #pragma unroll
        for (int o = 0; o < 12; o++) pv[o] = rsum2(acc[o]) + swt[OFF_BB2 + o];

        // ---- epilogue: exp(sigma), stable descending sort by w ----
        float4 pl[3]; float ws[3];
        #pragma unroll
        for (int k = 0; k < 3; k++) {
            pl[k] = make_float4(pv[4 * k], pv[4 * k + 1],
                                expf(pv[4 * k + 2]), expf(pv[4 * k + 3]));
            ws[k] = wv[k];
        }
        #define CSWAP(a_, b_)                                               \
            if (ws[b_] > ws[a_]) {                                          \
                float tw = ws[a_]; ws[a_] = ws[b_]; ws[b_] = tw;            \
                float4 tp = pl[a_]; pl[a_] = pl[b_]; pl[b_] = tp;           \
            }
        CSWAP(0, 1) CSWAP(1, 2) CSWAP(0, 1)
        #undef CSWAP

        // ---- stage 15 floats into per-warp smem (pad-17, conflict-free) ----
        float* op = myStage + lane * 17;
        #pragma unroll
        for (int k = 0; k < 3; k++) {
            op[5 * k + 0] = wv[k];
            op[5 * k + 1] = pl[k].x;
            op[5 * k + 2] = pl[k].y;
            op[5 * k + 3] = pl[k].z;
            op[5 * k + 4] = pl[k].w;
        }

        // ---- k_js and mask: direct stores (small) ----
        const size_t pidx = (size_t)b * NJ + joint;
        out[KJS_OFF + pidx] = (float)(am + 1);
        float* gm = out + MASK_OFF + pidx * 3;
        gm[0] = 1.0f;
        gm[1] = (am >= 1) ? 1.0f : 0.0f;
        gm[2] = (am >= 2) ? 1.0f : 0.0f;

        __syncwarp();

        // ---- flush: each STG.32 covers 2 point-chunks (15 lanes each) ----
        const size_t base = (size_t)tile * (TILE_B * NJ * 15) + (size_t)joint * 15;
        #pragma unroll
        for (int q = 0; q < 16; q++) {
            const int c = 2 * q + hi;                    // chunk = point-in-tile
            if (j15 < 15)
                out[base + (size_t)c * (NJ * 15) + j15] = myStage[c * 17 + j15];
        }
        __syncwarp();
    }
}

// ---------------------------------------------------------------------------
extern "C" void kernel_launch(void* const* d_in, const int* in_sizes, int n_in,
                              void* d_out, int out_size)
{
    const float* pred = (const float*)d_in[0];
    const float* kW1 = (const float*)d_in[1];
    const float* kb1 = (const float*)d_in[2];
    const float* kW2 = (const float*)d_in[3];
    const float* kb2 = (const float*)d_in[4];
    const float* wW1 = (const float*)d_in[5];
    const float* wb1 = (const float*)d_in[6];
    const float* wW2 = (const float*)d_in[7];
    const float* wb2 = (const float*)d_in[8];
    const float* bW1 = (const float*)d_in[9];
    const float* bb1 = (const float*)d_in[10];
    const float* bW2 = (const float*)d_in[11];
    const float* bb2 = (const float*)d_in[12];
    float* out = (float*)d_out;

    pack_weights<<<NJ, 128>>>(kW1, kb1, kW2, kb2,
                              wW1, wb1, wW2, wb2,
                              bW1, bb1, bW2, bb2);

    mlp_main<<<NJ * NBJ, 256>>>(pred, out);
}

// round 4
// speedup vs baseline: 1.3319x; 1.2236x over previous
#include <cuda_runtime.h>
#include <cstdint>

// ---------------------------------------------------------------------------
// B=32768, N=17 joints, D=2, K=3, H=64 (k/w MLPs), 2H=128 (b MLP)
// Outputs (flattened float32): out (B,N,K,5) | k_js (B,N) | mask (B,N,K)
// ---------------------------------------------------------------------------
#define NB        32768
#define NJ        17
#define TILE_B    32
#define NTILES    (NB / TILE_B)          // 1024
#define NPAIRS    (NTILES / 2)           // 512
#define NBJ       26                     // blocks per joint (17*26=442 blocks)
#define ITERS     3                      // pair-slots per warp (26*8*3=624>=512)

#define JSTRIDE   2836                   // floats per joint in packed weights
#define WFLOATS   (NJ * JSTRIDE)

// packed per-joint layout (floats):
//  [0,384):    kMLP rows, 32 rows x 12: [W1d0 pair, W1d1 pair | W2o0, W2o1 | W2o2, b1]
//  [384,768):  wMLP rows, same
//  [768,2816): bMLP rows, 64 rows x 32: [W1 pairs(4) | W2 o0..o11 pairs (24) | b1 pair, pad]
//  [2816,2819): kb2[3]  [2819,2822): wb2[3]  [2822,2834): bb2[12]
#define SEC_W     384
#define SEC_B     768
#define OFF_KB2   2816
#define OFF_WB2   2819
#define OFF_BB2   2822

#define KJS_OFF     8355840ull           // B*N*K*5
#define MASK_OFF    8912896ull

typedef unsigned long long ull;

static __device__ __forceinline__ ull pk2(float lo, float hi) {
    ull r; asm("mov.b64 %0,{%1,%2};" : "=l"(r) : "f"(lo), "f"(hi)); return r;
}
static __device__ __forceinline__ ull fma2(ull a, ull b, ull c) {
    ull d; asm("fma.rn.f32x2 %0,%1,%2,%3;" : "=l"(d) : "l"(a), "l"(b), "l"(c)); return d;
}
static __device__ __forceinline__ ull relu2(ull g) {
    float lo, hi; asm("mov.b64 {%0,%1},%2;" : "=f"(lo), "=f"(hi) : "l"(g));
    lo = fmaxf(lo, 0.f); hi = fmaxf(hi, 0.f);
    ull r; asm("mov.b64 %0,{%1,%2};" : "=l"(r) : "f"(lo), "f"(hi)); return r;
}
static __device__ __forceinline__ float rsum2(ull a) {
    float lo, hi; asm("mov.b64 {%0,%1},%2;" : "=f"(lo), "=f"(hi) : "l"(a));
    return lo + hi;
}

__device__ __align__(16) float g_packed[WFLOATS];

// ---------------------------------------------------------------------------
// Setup kernel: pack weights into f32x2-pair rows (17 blocks x 128 threads).
// ---------------------------------------------------------------------------
__global__ void pack_weights(
    const float* __restrict__ kW1, const float* __restrict__ kb1,
    const float* __restrict__ kW2, const float* __restrict__ kb2,
    const float* __restrict__ wW1, const float* __restrict__ wb1,
    const float* __restrict__ wW2, const float* __restrict__ wb2,
    const float* __restrict__ bW1, const float* __restrict__ bb1,
    const float* __restrict__ bW2, const float* __restrict__ bb2)
{
    const int n = blockIdx.x;
    const int t = threadIdx.x;
    float* dst = g_packed + n * JSTRIDE;

    if (t < 32) {                       // kMLP row jp = t
        const int jp = t, j = 2 * jp;
        float* r = dst + jp * 12;
        r[0] = kW1[n * 128 + j];          r[1] = kW1[n * 128 + j + 1];
        r[2] = kW1[n * 128 + 64 + j];     r[3] = kW1[n * 128 + 64 + j + 1];
        #pragma unroll
        for (int o = 0; o < 3; o++) {
            r[4 + 2 * o] = kW2[n * 192 + j * 3 + o];
            r[5 + 2 * o] = kW2[n * 192 + (j + 1) * 3 + o];
        }
        r[10] = kb1[n * 64 + j];          r[11] = kb1[n * 64 + j + 1];
    } else if (t < 64) {                // wMLP row jp = t-32
        const int jp = t - 32, j = 2 * jp;
        float* r = dst + SEC_W + jp * 12;
        r[0] = wW1[n * 128 + j];          r[1] = wW1[n * 128 + j + 1];
        r[2] = wW1[n * 128 + 64 + j];     r[3] = wW1[n * 128 + 64 + j + 1];
        #pragma unroll
        for (int o = 0; o < 3; o++) {
            r[4 + 2 * o] = wW2[n * 192 + j * 3 + o];
            r[5 + 2 * o] = wW2[n * 192 + (j + 1) * 3 + o];
        }
        r[10] = wb1[n * 64 + j];          r[11] = wb1[n * 64 + j + 1];
    } else {                            // bMLP row jp = t-64
        const int jp = t - 64, j = 2 * jp;
        float* r = dst + SEC_B + jp * 32;
        r[0] = bW1[n * 256 + j];          r[1] = bW1[n * 256 + j + 1];
        r[2] = bW1[n * 256 + 128 + j];    r[3] = bW1[n * 256 + 128 + j + 1];
        #pragma unroll
        for (int o = 0; o < 12; o++) {
            r[4 + 2 * o] = bW2[n * 1536 + j * 12 + o];
            r[5 + 2 * o] = bW2[n * 1536 + (j + 1) * 12 + o];
        }
        r[28] = bb1[n * 128 + j];         r[29] = bb1[n * 128 + j + 1];
        r[30] = 0.f; r[31] = 0.f;
    }
    if (t == 0) {
        #pragma unroll
        for (int o = 0; o < 3; o++)  { dst[OFF_KB2 + o] = kb2[n * 3 + o];
                                       dst[OFF_WB2 + o] = wb2[n * 3 + o]; }
        #pragma unroll
        for (int o = 0; o < 12; o++)   dst[OFF_BB2 + o] = bb2[n * 12 + o];
    }
}

// Dual-point 64-hidden MLP head: 3x LDS.128 per row shared by both points.
static __device__ __forceinline__ void mlp64_2(const float* __restrict__ rows,
                                               ull X0a, ull X1a, ull X0b, ull X1b,
                                               float* oa, float* ob)
{
    ull a0 = 0, a1 = 0, a2 = 0, c0 = 0, c1 = 0, c2 = 0;
    #pragma unroll 4
    for (int jp = 0; jp < 32; jp++) {
        const float* r = rows + jp * 12;
        ulonglong2 q0 = *(const ulonglong2*)(r);       // W1 d0 pair, d1 pair
        ulonglong2 q1 = *(const ulonglong2*)(r + 4);   // W2 o0, o1 pairs
        ulonglong2 q2 = *(const ulonglong2*)(r + 8);   // W2 o2 pair, b1 pair
        ull ha = relu2(fma2(X0a, q0.x, fma2(X1a, q0.y, q2.y)));
        ull hb = relu2(fma2(X0b, q0.x, fma2(X1b, q0.y, q2.y)));
        a0 = fma2(ha, q1.x, a0);  c0 = fma2(hb, q1.x, c0);
        a1 = fma2(ha, q1.y, a1);  c1 = fma2(hb, q1.y, c1);
        a2 = fma2(ha, q2.x, a2);  c2 = fma2(hb, q2.x, c2);
    }
    oa[0] = rsum2(a0); oa[1] = rsum2(a1); oa[2] = rsum2(a2);
    ob[0] = rsum2(c0); ob[1] = rsum2(c1); ob[2] = rsum2(c2);
}

// Per-point epilogue: argmax, softmax, exp(sigma), stable descending sort.
static __device__ __forceinline__ void finish(const float kl[3], const float wl[3],
                                              const float pv[12],
                                              float v[15], int& am)
{
    am = 0; float bm = kl[0];
    if (kl[1] > bm) { bm = kl[1]; am = 1; }
    if (kl[2] > bm) { bm = kl[2]; am = 2; }

    float m  = fmaxf(wl[0], fmaxf(wl[1], wl[2]));
    float e0 = expf(wl[0] - m), e1 = expf(wl[1] - m), e2 = expf(wl[2] - m);
    float inv = 1.0f / (e0 + e1 + e2);
    float wv[3] = { e0 * inv, e1 * inv, e2 * inv };

    float4 pl[3]; float ws[3];
    #pragma unroll
    for (int k = 0; k < 3; k++) {
        pl[k] = make_float4(pv[4 * k], pv[4 * k + 1],
                            expf(pv[4 * k + 2]), expf(pv[4 * k + 3]));
        ws[k] = wv[k];
    }
    // stable descending sort by w (strict >): matches stable jnp.argsort(-w)
    #define CSWAP(i_, j_)                                               \
        if (ws[j_] > ws[i_]) {                                          \
            float tw = ws[i_]; ws[i_] = ws[j_]; ws[j_] = tw;            \
            float4 tp = pl[i_]; pl[i_] = pl[j_]; pl[j_] = tp;           \
        }
    CSWAP(0, 1) CSWAP(1, 2) CSWAP(0, 1)
    #undef CSWAP

    #pragma unroll
    for (int k = 0; k < 3; k++) {
        v[5 * k + 0] = wv[k];
        v[5 * k + 1] = pl[k].x;
        v[5 * k + 2] = pl[k].y;
        v[5 * k + 3] = pl[k].z;
        v[5 * k + 4] = pl[k].w;
    }
}

// ---------------------------------------------------------------------------
// Main kernel: 1 joint/block, 256 threads (8 warps), 3 blocks/SM (24 warps),
// 2 points per thread sharing every weight load. Warps independent in loop.
// ---------------------------------------------------------------------------
__global__ void __launch_bounds__(256, 3)
mlp_main(const float* __restrict__ pred, float* __restrict__ out)
{
    __shared__ float swt[JSTRIDE];                 // this joint's packed weights
    __shared__ float sStage[8][32 * 17];           // per-warp staging, pad 17

    const int joint = blockIdx.x % NJ;
    const int blk   = blockIdx.x / NJ;             // 0..NBJ-1
    const int wid   = threadIdx.x >> 5;
    const int lane  = threadIdx.x & 31;

    {   // stage this joint's weights into smem (coalesced float4)
        const float4* src = (const float4*)(g_packed + joint * JSTRIDE);
        float4* dst = (float4*)swt;
        #pragma unroll
        for (int i = threadIdx.x; i < JSTRIDE / 4; i += 256) dst[i] = src[i];
    }
    __syncthreads();

    const float kb2a = swt[OFF_KB2], kb2b = swt[OFF_KB2 + 1], kb2c = swt[OFF_KB2 + 2];
    const float wb2a = swt[OFF_WB2], wb2b = swt[OFF_WB2 + 1], wb2c = swt[OFF_WB2 + 2];

    float* myStage = sStage[wid];
    const int j15 = lane & 15;
    const int hi  = lane >> 4;          // 0 for lanes 0-15, 1 for 16-31

    for (int i = 0; i < ITERS; i++) {
        const int pr = blk + NBJ * (wid + 8 * i);
        if (pr >= NPAIRS) break;
        const int ta = 2 * pr, tb = ta + 1;
        const int ba = ta * TILE_B + lane;
        const int bb = tb * TILE_B + lane;

        const float2 xa = *(const float2*)(pred + ((size_t)ba * NJ + joint) * 2);
        const float2 xb = *(const float2*)(pred + ((size_t)bb * NJ + joint) * 2);
        const ull X0a = pk2(xa.x, xa.x), X1a = pk2(xa.y, xa.y);
        const ull X0b = pk2(xb.x, xb.x), X1b = pk2(xb.y, xb.y);

        // ---- kMLP ----
        float kla[3], klb[3];
        mlp64_2(swt, X0a, X1a, X0b, X1b, kla, klb);
        kla[0] += kb2a; kla[1] += kb2b; kla[2] += kb2c;
        klb[0] += kb2a; klb[1] += kb2b; klb[2] += kb2c;

        // ---- wMLP ----
        float wla[3], wlb[3];
        mlp64_2(swt + SEC_W, X0a, X1a, X0b, X1b, wla, wlb);
        wla[0] += wb2a; wla[1] += wb2b; wla[2] += wb2c;
        wlb[0] += wb2a; wlb[1] += wb2b; wlb[2] += wb2c;

        // ---- bMLP (2 -> 128 -> 12), dual point, weights loaded once ----
        ull acca[12], accb[12];
        #pragma unroll
        for (int o = 0; o < 12; o++) { acca[o] = 0; accb[o] = 0; }
        #pragma unroll 2
        for (int jp = 0; jp < 64; jp++) {
            const float* r = swt + SEC_B + jp * 32;
            ulonglong2 q0 = *(const ulonglong2*)(r);
            ulonglong2 q1 = *(const ulonglong2*)(r + 4);
            ulonglong2 q2 = *(const ulonglong2*)(r + 8);
            ulonglong2 q3 = *(const ulonglong2*)(r + 12);
            ulonglong2 q4 = *(const ulonglong2*)(r + 16);
            ulonglong2 q5 = *(const ulonglong2*)(r + 20);
            ulonglong2 q6 = *(const ulonglong2*)(r + 24);
            ull cb = *(const ull*)(r + 28);
            ull ha = relu2(fma2(X0a, q0.x, fma2(X1a, q0.y, cb)));
            ull hb = relu2(fma2(X0b, q0.x, fma2(X1b, q0.y, cb)));
            acca[0]  = fma2(ha, q1.x, acca[0]);  accb[0]  = fma2(hb, q1.x, accb[0]);
            acca[1]  = fma2(ha, q1.y, acca[1]);  accb[1]  = fma2(hb, q1.y, accb[1]);
            acca[2]  = fma2(ha, q2.x, acca[2]);  accb[2]  = fma2(hb, q2.x, accb[2]);
            acca[3]  = fma2(ha, q2.y, acca[3]);  accb[3]  = fma2(hb, q2.y, accb[3]);
            acca[4]  = fma2(ha, q3.x, acca[4]);  accb[4]  = fma2(hb, q3.x, accb[4]);
            acca[5]  = fma2(ha, q3.y, acca[5]);  accb[5]  = fma2(hb, q3.y, accb[5]);
            acca[6]  = fma2(ha, q4.x, acca[6]);  accb[6]  = fma2(hb, q4.x, accb[6]);
            acca[7]  = fma2(ha, q4.y, acca[7]);  accb[7]  = fma2(hb, q4.y, accb[7]);
            acca[8]  = fma2(ha, q5.x, acca[8]);  accb[8]  = fma2(hb, q5.x, accb[8]);
            acca[9]  = fma2(ha, q5.y, acca[9]);  accb[9]  = fma2(hb, q5.y, accb[9]);
            acca[10] = fma2(ha, q6.x, acca[10]); accb[10] = fma2(hb, q6.x, accb[10]);
            acca[11] = fma2(ha, q6.y, acca[11]); accb[11] = fma2(hb, q6.y, accb[11]);
        }
        float pva[12], pvb[12];
        #pragma unroll
        for (int o = 0; o < 12; o++) {
            const float bias = swt[OFF_BB2 + o];
            pva[o] = rsum2(acca[o]) + bias;
            pvb[o] = rsum2(accb[o]) + bias;
        }

        // ---- tile a: epilogue + stage + flush ----
        {
            float va[15]; int ama;
            finish(kla, wla, pva, va, ama);
            float* op = myStage + lane * 17;
            #pragma unroll
            for (int k = 0; k < 15; k++) op[k] = va[k];
            const size_t pidx = (size_t)ba * NJ + joint;
            out[KJS_OFF + pidx] = (float)(ama + 1);
            float* gm = out + MASK_OFF + pidx * 3;
            gm[0] = 1.0f;
            gm[1] = (ama >= 1) ? 1.0f : 0.0f;
            gm[2] = (ama >= 2) ? 1.0f : 0.0f;
            __syncwarp();
            const size_t base = (size_t)ta * (TILE_B * NJ * 15) + (size_t)joint * 15;
            #pragma unroll
            for (int q = 0; q < 16; q++) {
                const int c = 2 * q + hi;
                if (j15 < 15)
                    out[base + (size_t)c * (NJ * 15) + j15] = myStage[c * 17 + j15];
            }
            __syncwarp();
        }

        // ---- tile b: epilogue + stage + flush ----
        {
            float vb[15]; int amb;
            finish(klb, wlb, pvb, vb, amb);
            float* op = myStage + lane * 17;
            #pragma unroll
            for (int k = 0; k < 15; k++) op[k] = vb[k];
            const size_t pidx = (size_t)bb * NJ + joint;
            out[KJS_OFF + pidx] = (float)(amb + 1);
            float* gm = out + MASK_OFF + pidx * 3;
            gm[0] = 1.0f;
            gm[1] = (amb >= 1) ? 1.0f : 0.0f;
            gm[2] = (amb >= 2) ? 1.0f : 0.0f;
            __syncwarp();
            const size_t base = (size_t)tb * (TILE_B * NJ * 15) + (size_t)joint * 15;
            #pragma unroll
            for (int q = 0; q < 16; q++) {
                const int c = 2 * q + hi;
                if (j15 < 15)
                    out[base + (size_t)c * (NJ * 15) + j15] = myStage[c * 17 + j15];
            }
            __syncwarp();
        }
    }
}

// ---------------------------------------------------------------------------
extern "C" void kernel_launch(void* const* d_in, const int* in_sizes, int n_in,
                              void* d_out, int out_size)
{
    const float* pred = (const float*)d_in[0];
    const float* kW1 = (const float*)d_in[1];
    const float* kb1 = (const float*)d_in[2];
    const float* kW2 = (const float*)d_in[3];
    const float* kb2 = (const float*)d_in[4];
    const float* wW1 = (const float*)d_in[5];
    const float* wb1 = (const float*)d_in[6];
    const float* wW2 = (const float*)d_in[7];
    const float* wb2 = (const float*)d_in[8];
    const float* bW1 = (const float*)d_in[9];
    const float* bb1 = (const float*)d_in[10];
    const float* bW2 = (const float*)d_in[11];
    const float* bb2 = (const float*)d_in[12];
    float* out = (float*)d_out;

    pack_weights<<<NJ, 128>>>(kW1, kb1, kW2, kb2,
                              wW1, wb1, wW2, wb2,
                              bW1, bb1, bW2, bb2);

    mlp_main<<<NJ * NBJ, 256>>>(pred, out);
}

// round 5
// speedup vs baseline: 1.4314x; 1.0747x over previous
#include <cuda_runtime.h>
#include <cstdint>

// ---------------------------------------------------------------------------
// B=32768, N=17 joints, D=2, K=3, H=64 (k/w MLPs), 2H=128 (b MLP)
// Outputs (flattened float32): out (B,N,K,5) | k_js (B,N) | mask (B,N,K)
// ---------------------------------------------------------------------------
#define NB        32768
#define NJ        17
#define TILE_B    32
#define NTILES    (NB / TILE_B)          // 1024
#define NPAIRS    (NTILES / 2)           // 512
#define NBJ       128                    // blocks per joint (128*4 warps = 512 pairs)
#define NWARPS    4                      // warps per block

#define JSTRIDE   2836                   // floats per joint in packed weights
#define WFLOATS   (NJ * JSTRIDE)

// packed per-joint layout (floats):
//  [0,384):    kMLP rows, 32 rows x 12: [W1d0 pair, W1d1 pair | W2o0, W2o1 | W2o2, b1]
//  [384,768):  wMLP rows, same
//  [768,2816): bMLP rows, 64 rows x 32: [W1 pairs(4) | W2 o0..o11 pairs (24) | b1 pair, pad]
//  [2816,2819): kb2[3]  [2819,2822): wb2[3]  [2822,2834): bb2[12]
#define SEC_W     384
#define SEC_B     768
#define OFF_KB2   2816
#define OFF_WB2   2819
#define OFF_BB2   2822

#define KJS_OFF     8355840ull           // B*N*K*5
#define MASK_OFF    8912896ull

typedef unsigned long long ull;

static __device__ __forceinline__ ull pk2(float lo, float hi) {
    ull r; asm("mov.b64 %0,{%1,%2};" : "=l"(r) : "f"(lo), "f"(hi)); return r;
}
static __device__ __forceinline__ ull fma2(ull a, ull b, ull c) {
    ull d; asm("fma.rn.f32x2 %0,%1,%2,%3;" : "=l"(d) : "l"(a), "l"(b), "l"(c)); return d;
}
static __device__ __forceinline__ ull relu2(ull g) {
    float lo, hi; asm("mov.b64 {%0,%1},%2;" : "=f"(lo), "=f"(hi) : "l"(g));
    lo = fmaxf(lo, 0.f); hi = fmaxf(hi, 0.f);
    ull r; asm("mov.b64 %0,{%1,%2};" : "=l"(r) : "f"(lo), "f"(hi)); return r;
}
static __device__ __forceinline__ float rsum2(ull a) {
    float lo, hi; asm("mov.b64 {%0,%1},%2;" : "=f"(lo), "=f"(hi) : "l"(a));
    return lo + hi;
}

__device__ __align__(16) float g_packed[WFLOATS];

// ---------------------------------------------------------------------------
// Setup kernel: pack weights into f32x2-pair rows (17 blocks x 128 threads).
// ---------------------------------------------------------------------------
__global__ void pack_weights(
    const float* __restrict__ kW1, const float* __restrict__ kb1,
    const float* __restrict__ kW2, const float* __restrict__ kb2,
    const float* __restrict__ wW1, const float* __restrict__ wb1,
    const float* __restrict__ wW2, const float* __restrict__ wb2,
    const float* __restrict__ bW1, const float* __restrict__ bb1,
    const float* __restrict__ bW2, const float* __restrict__ bb2)
{
    const int n = blockIdx.x;
    const int t = threadIdx.x;
    float* dst = g_packed + n * JSTRIDE;

    if (t < 32) {                       // kMLP row jp = t
        const int jp = t, j = 2 * jp;
        float* r = dst + jp * 12;
        r[0] = kW1[n * 128 + j];          r[1] = kW1[n * 128 + j + 1];
        r[2] = kW1[n * 128 + 64 + j];     r[3] = kW1[n * 128 + 64 + j + 1];
        #pragma unroll
        for (int o = 0; o < 3; o++) {
            r[4 + 2 * o] = kW2[n * 192 + j * 3 + o];
            r[5 + 2 * o] = kW2[n * 192 + (j + 1) * 3 + o];
        }
        r[10] = kb1[n * 64 + j];          r[11] = kb1[n * 64 + j + 1];
    } else if (t < 64) {                // wMLP row jp = t-32
        const int jp = t - 32, j = 2 * jp;
        float* r = dst + SEC_W + jp * 12;
        r[0] = wW1[n * 128 + j];          r[1] = wW1[n * 128 + j + 1];
        r[2] = wW1[n * 128 + 64 + j];     r[3] = wW1[n * 128 + 64 + j + 1];
        #pragma unroll
        for (int o = 0; o < 3; o++) {
            r[4 + 2 * o] = wW2[n * 192 + j * 3 + o];
            r[5 + 2 * o] = wW2[n * 192 + (j + 1) * 3 + o];
        }
        r[10] = wb1[n * 64 + j];          r[11] = wb1[n * 64 + j + 1];
    } else {                            // bMLP row jp = t-64
        const int jp = t - 64, j = 2 * jp;
        float* r = dst + SEC_B + jp * 32;
        r[0] = bW1[n * 256 + j];          r[1] = bW1[n * 256 + j + 1];
        r[2] = bW1[n * 256 + 128 + j];    r[3] = bW1[n * 256 + 128 + j + 1];
        #pragma unroll
        for (int o = 0; o < 12; o++) {
            r[4 + 2 * o] = bW2[n * 1536 + j * 12 + o];
            r[5 + 2 * o] = bW2[n * 1536 + (j + 1) * 12 + o];
        }
        r[28] = bb1[n * 128 + j];         r[29] = bb1[n * 128 + j + 1];
        r[30] = 0.f; r[31] = 0.f;
    }
    if (t == 0) {
        #pragma unroll
        for (int o = 0; o < 3; o++)  { dst[OFF_KB2 + o] = kb2[n * 3 + o];
                                       dst[OFF_WB2 + o] = wb2[n * 3 + o]; }
        #pragma unroll
        for (int o = 0; o < 12; o++)   dst[OFF_BB2 + o] = bb2[n * 12 + o];
    }
}

// Dual-point 64-hidden MLP head: 3x LDS.128 per row shared by both points.
static __device__ __forceinline__ void mlp64_2(const float* __restrict__ rows,
                                               ull X0a, ull X1a, ull X0b, ull X1b,
                                               float* oa, float* ob)
{
    ull a0 = 0, a1 = 0, a2 = 0, c0 = 0, c1 = 0, c2 = 0;
    #pragma unroll 4
    for (int jp = 0; jp < 32; jp++) {
        const float* r = rows + jp * 12;
        ulonglong2 q0 = *(const ulonglong2*)(r);       // W1 d0 pair, d1 pair
        ulonglong2 q1 = *(const ulonglong2*)(r + 4);   // W2 o0, o1 pairs
        ulonglong2 q2 = *(const ulonglong2*)(r + 8);   // W2 o2 pair, b1 pair
        ull ha = relu2(fma2(X0a, q0.x, fma2(X1a, q0.y, q2.y)));
        ull hb = relu2(fma2(X0b, q0.x, fma2(X1b, q0.y, q2.y)));
        a0 = fma2(ha, q1.x, a0);  c0 = fma2(hb, q1.x, c0);
        a1 = fma2(ha, q1.y, a1);  c1 = fma2(hb, q1.y, c1);
        a2 = fma2(ha, q2.x, a2);  c2 = fma2(hb, q2.x, c2);
    }
    oa[0] = rsum2(a0); oa[1] = rsum2(a1); oa[2] = rsum2(a2);
    ob[0] = rsum2(c0); ob[1] = rsum2(c1); ob[2] = rsum2(c2);
}

// Per-point epilogue: argmax, softmax, exp(sigma), stable descending sort.
static __device__ __forceinline__ void finish(const float kl[3], const float wl[3],
                                              const float pv[12],
                                              float v[15], int& am)
{
    am = 0; float bm = kl[0];
    if (kl[1] > bm) { bm = kl[1]; am = 1; }
    if (kl[2] > bm) { bm = kl[2]; am = 2; }

    float m  = fmaxf(wl[0], fmaxf(wl[1], wl[2]));
    float e0 = expf(wl[0] - m), e1 = expf(wl[1] - m), e2 = expf(wl[2] - m);
    float inv = 1.0f / (e0 + e1 + e2);
    float wv[3] = { e0 * inv, e1 * inv, e2 * inv };

    float4 pl[3]; float ws[3];
    #pragma unroll
    for (int k = 0; k < 3; k++) {
        pl[k] = make_float4(pv[4 * k], pv[4 * k + 1],
                            expf(pv[4 * k + 2]), expf(pv[4 * k + 3]));
        ws[k] = wv[k];
    }
    // stable descending sort by w (strict >): matches stable jnp.argsort(-w)
    #define CSWAP(i_, j_)                                               \
        if (ws[j_] > ws[i_]) {                                          \
            float tw = ws[i_]; ws[i_] = ws[j_]; ws[j_] = tw;            \
            float4 tp = pl[i_]; pl[i_] = pl[j_]; pl[j_] = tp;           \
        }
    CSWAP(0, 1) CSWAP(1, 2) CSWAP(0, 1)
    #undef CSWAP

    #pragma unroll
    for (int k = 0; k < 3; k++) {
        v[5 * k + 0] = wv[k];
        v[5 * k + 1] = pl[k].x;
        v[5 * k + 2] = pl[k].y;
        v[5 * k + 3] = pl[k].z;
        v[5 * k + 4] = pl[k].w;
    }
}

// ---------------------------------------------------------------------------
// Main kernel: 128 threads (4 warps), 6 blocks/SM -> 24 warps/SM.
// Each warp handles exactly ONE pair of tiles (2 points/thread, weights
// loaded once per pair). Zero idle warp-slots, no guards.
// ---------------------------------------------------------------------------
__global__ void __launch_bounds__(128, 6)
mlp_main(const float* __restrict__ pred, float* __restrict__ out)
{
    __shared__ float swt[JSTRIDE];                 // this joint's packed weights
    __shared__ float sStage[NWARPS][32 * 17];      // per-warp staging, pad 17

    const int joint = blockIdx.x % NJ;
    const int blk   = blockIdx.x / NJ;             // 0..NBJ-1
    const int wid   = threadIdx.x >> 5;
    const int lane  = threadIdx.x & 31;

    {   // stage this joint's weights into smem (coalesced float4)
        const float4* src = (const float4*)(g_packed + joint * JSTRIDE);
        float4* dst = (float4*)swt;
        #pragma unroll
        for (int i = threadIdx.x; i < JSTRIDE / 4; i += 128) dst[i] = src[i];
    }
    __syncthreads();

    const float kb2a = swt[OFF_KB2], kb2b = swt[OFF_KB2 + 1], kb2c = swt[OFF_KB2 + 2];
    const float wb2a = swt[OFF_WB2], wb2b = swt[OFF_WB2 + 1], wb2c = swt[OFF_WB2 + 2];

    float* myStage = sStage[wid];
    const int j15 = lane & 15;
    const int hi  = lane >> 4;          // 0 for lanes 0-15, 1 for 16-31

    const int pr = blk * NWARPS + wid;  // 0..511, exact cover of all pairs
    const int ta = 2 * pr, tb = ta + 1;
    const int ba = ta * TILE_B + lane;
    const int bb = tb * TILE_B + lane;

    const float2 xa = *(const float2*)(pred + ((size_t)ba * NJ + joint) * 2);
    const float2 xb = *(const float2*)(pred + ((size_t)bb * NJ + joint) * 2);
    const ull X0a = pk2(xa.x, xa.x), X1a = pk2(xa.y, xa.y);
    const ull X0b = pk2(xb.x, xb.x), X1b = pk2(xb.y, xb.y);

    // ---- kMLP ----
    float kla[3], klb[3];
    mlp64_2(swt, X0a, X1a, X0b, X1b, kla, klb);
    kla[0] += kb2a; kla[1] += kb2b; kla[2] += kb2c;
    klb[0] += kb2a; klb[1] += kb2b; klb[2] += kb2c;

    // ---- wMLP ----
    float wla[3], wlb[3];
    mlp64_2(swt + SEC_W, X0a, X1a, X0b, X1b, wla, wlb);
    wla[0] += wb2a; wla[1] += wb2b; wla[2] += wb2c;
    wlb[0] += wb2a; wlb[1] += wb2b; wlb[2] += wb2c;

    // ---- bMLP (2 -> 128 -> 12), dual point, weights loaded once ----
    ull acca[12], accb[12];
    #pragma unroll
    for (int o = 0; o < 12; o++) { acca[o] = 0; accb[o] = 0; }
    #pragma unroll 2
    for (int jp = 0; jp < 64; jp++) {
        const float* r = swt + SEC_B + jp * 32;
        ulonglong2 q0 = *(const ulonglong2*)(r);
        ulonglong2 q1 = *(const ulonglong2*)(r + 4);
        ulonglong2 q2 = *(const ulonglong2*)(r + 8);
        ulonglong2 q3 = *(const ulonglong2*)(r + 12);
        ulonglong2 q4 = *(const ulonglong2*)(r + 16);
        ulonglong2 q5 = *(const ulonglong2*)(r + 20);
        ulonglong2 q6 = *(const ulonglong2*)(r + 24);
        ull cb = *(const ull*)(r + 28);
        ull ha = relu2(fma2(X0a, q0.x, fma2(X1a, q0.y, cb)));
        ull hb = relu2(fma2(X0b, q0.x, fma2(X1b, q0.y, cb)));
        acca[0]  = fma2(ha, q1.x, acca[0]);  accb[0]  = fma2(hb, q1.x, accb[0]);
        acca[1]  = fma2(ha, q1.y, acca[1]);  accb[1]  = fma2(hb, q1.y, accb[1]);
        acca[2]  = fma2(ha, q2.x, acca[2]);  accb[2]  = fma2(hb, q2.x, accb[2]);
        acca[3]  = fma2(ha, q2.y, acca[3]);  accb[3]  = fma2(hb, q2.y, accb[3]);
        acca[4]  = fma2(ha, q3.x, acca[4]);  accb[4]  = fma2(hb, q3.x, accb[4]);
        acca[5]  = fma2(ha, q3.y, acca[5]);  accb[5]  = fma2(hb, q3.y, accb[5]);
        acca[6]  = fma2(ha, q4.x, acca[6]);  accb[6]  = fma2(hb, q4.x, accb[6]);
        acca[7]  = fma2(ha, q4.y, acca[7]);  accb[7]  = fma2(hb, q4.y, accb[7]);
        acca[8]  = fma2(ha, q5.x, acca[8]);  accb[8]  = fma2(hb, q5.x, accb[8]);
        acca[9]  = fma2(ha, q5.y, acca[9]);  accb[9]  = fma2(hb, q5.y, accb[9]);
        acca[10] = fma2(ha, q6.x, acca[10]); accb[10] = fma2(hb, q6.x, accb[10]);
        acca[11] = fma2(ha, q6.y, acca[11]); accb[11] = fma2(hb, q6.y, accb[11]);
    }
    float pva[12], pvb[12];
    #pragma unroll
    for (int o = 0; o < 12; o++) {
        const float bias = swt[OFF_BB2 + o];
        pva[o] = rsum2(acca[o]) + bias;
        pvb[o] = rsum2(accb[o]) + bias;
    }

    // ---- tile a: epilogue + stage + flush ----
    {
        float va[15]; int ama;
        finish(kla, wla, pva, va, ama);
        float* op = myStage + lane * 17;
        #pragma unroll
        for (int k = 0; k < 15; k++) op[k] = va[k];
        const size_t pidx = (size_t)ba * NJ + joint;
        out[KJS_OFF + pidx] = (float)(ama + 1);
        float* gm = out + MASK_OFF + pidx * 3;
        gm[0] = 1.0f;
        gm[1] = (ama >= 1) ? 1.0f : 0.0f;
        gm[2] = (ama >= 2) ? 1.0f : 0.0f;
        __syncwarp();
        const size_t base = (size_t)ta * (TILE_B * NJ * 15) + (size_t)joint * 15;
        #pragma unroll
        for (int q = 0; q < 16; q++) {
            const int c = 2 * q + hi;
            if (j15 < 15)
                out[base + (size_t)c * (NJ * 15) + j15] = myStage[c * 17 + j15];
        }
        __syncwarp();
    }

    // ---- tile b: epilogue + stage + flush ----
    {
        float vb[15]; int amb;
        finish(klb, wlb, pvb, vb, amb);
        float* op = myStage + lane * 17;
        #pragma unroll
        for (int k = 0; k < 15; k++) op[k] = vb[k];
        const size_t pidx = (size_t)bb * NJ + joint;
        out[KJS_OFF + pidx] = (float)(amb + 1);
        float* gm = out + MASK_OFF + pidx * 3;
        gm[0] = 1.0f;
        gm[1] = (amb >= 1) ? 1.0f : 0.0f;
        gm[2] = (amb >= 2) ? 1.0f : 0.0f;
        __syncwarp();
        const size_t base = (size_t)tb * (TILE_B * NJ * 15) + (size_t)joint * 15;
        #pragma unroll
        for (int q = 0; q < 16; q++) {
            const int c = 2 * q + hi;
            if (j15 < 15)
                out[base + (size_t)c * (NJ * 15) + j15] = myStage[c * 17 + j15];
        }
        __syncwarp();
    }
}

// ---------------------------------------------------------------------------
extern "C" void kernel_launch(void* const* d_in, const int* in_sizes, int n_in,
                              void* d_out, int out_size)
{
    const float* pred = (const float*)d_in[0];
    const float* kW1 = (const float*)d_in[1];
    const float* kb1 = (const float*)d_in[2];
    const float* kW2 = (const float*)d_in[3];
    const float* kb2 = (const float*)d_in[4];
    const float* wW1 = (const float*)d_in[5];
    const float* wb1 = (const float*)d_in[6];
    const float* wW2 = (const float*)d_in[7];
    const float* wb2 = (const float*)d_in[8];
    const float* bW1 = (const float*)d_in[9];
    const float* bb1 = (const float*)d_in[10];
    const float* bW2 = (const float*)d_in[11];
    const float* bb2 = (const float*)d_in[12];
    float* out = (float*)d_out;

    pack_weights<<<NJ, 128>>>(kW1, kb1, kW2, kb2,
                              wW1, wb1, wW2, wb2,
                              bW1, bb1, bW2, bb2);

    mlp_main<<<NJ * NBJ, 128>>>(pred, out);
}